// round 14
// baseline (speedup 1.0000x reference)
#include <cuda_runtime.h>
#include <cuda_bf16.h>

#define Bv 2
#define Cv 36
#define Hv 512
#define Wv 512
#define Kv 9

// Transposed features fp32: [B, H, W, C]; one pixel = 144B contiguous.
__device__ float g_featT[(size_t)Bv * Hv * Wv * Cv];

// ---------------------------------------------------------------------------
// Transpose [B,C,H,W] -> [B,H,W,C]; float4 reads AND float4 writes.
// ---------------------------------------------------------------------------
__global__ __launch_bounds__(256) void transpose_kernel(const float* __restrict__ feat) {
    __shared__ float tile[Cv][129];
    int b = blockIdx.z;
    int h = blockIdx.y;
    int w0 = blockIdx.x * 128;

    const float4* src = reinterpret_cast<const float4*>(feat);
    for (int i = threadIdx.x; i < Cv * 32; i += 256) {
        int c  = i >> 5;
        int w4 = i & 31;
        float4 v = src[((((size_t)b * Cv + c) * Hv + h) * Wv + w0) / 4 + w4];
        tile[c][4 * w4 + 0] = v.x;
        tile[c][4 * w4 + 1] = v.y;
        tile[c][4 * w4 + 2] = v.z;
        tile[c][4 * w4 + 3] = v.w;
    }
    __syncthreads();

    float4* outp = reinterpret_cast<float4*>(
        g_featT + (((size_t)b * Hv + h) * Wv + w0) * Cv);
    for (int e = threadIdx.x; e < 128 * 9; e += 256) {
        int w = e / 9;
        int q = e - w * 9;
        float4 v;
        v.x = tile[4 * q + 0][w];
        v.y = tile[4 * q + 1][w];
        v.z = tile[4 * q + 2][w];
        v.w = tile[4 * q + 3][w];
        outp[e] = v;
    }
}

// ---------------------------------------------------------------------------
// Eval kernel, double-buffered candidate pipeline. Block = 128 threads =
// 4 warps; warp owns 32 x-consecutive pixels. Load-phase parameters
// (off, wx, wy) are passed cross-lane through a per-warp smem table read
// with one LDS.128 broadcast per iteration — no shuffles on the LDG
// address path.
// ---------------------------------------------------------------------------
__global__ __launch_bounds__(128, 4) void eval_kernel(
    const float* __restrict__ feat,   // original [B,C,H,W]
    const float* __restrict__ offx,
    const float* __restrict__ offy,
    float* __restrict__ out)
{
    __shared__ float  stage[4][2][32 * 36];
    __shared__ float4 ptab[4][2][32];   // (off bits, wx, wy, -) per pixel

    const int tid  = blockIdx.x * 128 + threadIdx.x;
    const int lane = threadIdx.x & 31;
    const int wid  = threadIdx.x >> 5;
    const int x = tid & (Wv - 1);
    const int y = (tid >> 9) & (Hv - 1);
    const int b = tid >> 18;

    const char* fb = (const char*)g_featT;
    const unsigned rowstride = (unsigned)(Wv * Cv * 4);   // next y-row

    // ---- F: 36 coalesced scalar loads from the original layout ----
    float F[Cv];
    {
        const float* fp = feat + (size_t)b * (Cv * Hv * Wv) + (size_t)y * Wv + x;
#pragma unroll
        for (int c = 0; c < Cv; c++)
            F[c] = __ldg(fp + (size_t)c * (Hv * Wv));
    }

    // Compute this lane's sample params for one candidate and publish them.
    auto publish = [&](float oxk, float oyk, int parity) {
        float rx = fminf(fmaxf((float)x + oxk, 0.f), (float)(Wv - 1));
        float ry = fminf(fmaxf((float)y + oyk, 0.f), (float)(Hv - 1));
        int xb = min((int)floorf(rx), Wv - 2);
        int yb = min((int)floorf(ry), Hv - 2);
        float wx = rx - (float)xb;
        float wy = ry - (float)yb;
        unsigned off = (unsigned)((b * Hv + yb) * Wv + xb) * 144u;
        ptab[wid][parity][lane] = make_float4(__uint_as_float(off), wx, wy, 0.f);
    };

    // Load phase: 9 full-width iterations over 288 (pixel, channel-quad)
    // slots; params via LDS.128 broadcast.
    auto load_phase = [&](int parity, float* dst) {
        const float4* pt = ptab[wid][parity];
#pragma unroll 3
        for (int i = 0; i < 9; i++) {
            int f = 32 * i + lane;
            int p = f / 9;             // pixel within warp
            int j = f - 9 * p;         // channel-quad (0..8)
            float4 prm = pt[p];
            unsigned off_p = __float_as_uint(prm.x);
            float wx_p = prm.y;
            float wy_p = prm.z;
            const char* base = fb + off_p + ((unsigned)j << 4);
            float4 r0l = *reinterpret_cast<const float4*>(base);                    // yb  , xb
            float4 r0h = *reinterpret_cast<const float4*>(base + 144);              // yb  , xb+1
            float4 r1l = *reinterpret_cast<const float4*>(base + rowstride);        // yb+1, xb
            float4 r1h = *reinterpret_cast<const float4*>(base + rowstride + 144);  // yb+1, xb+1
            float4 a;
            {
                float tl = fmaf(wy_p, r1l.x - r0l.x, r0l.x);
                float th = fmaf(wy_p, r1h.x - r0h.x, r0h.x);
                a.x = fmaf(wx_p, th - tl, tl);
            }
            {
                float tl = fmaf(wy_p, r1l.y - r0l.y, r0l.y);
                float th = fmaf(wy_p, r1h.y - r0h.y, r0h.y);
                a.y = fmaf(wx_p, th - tl, tl);
            }
            {
                float tl = fmaf(wy_p, r1l.z - r0l.z, r0l.z);
                float th = fmaf(wy_p, r1h.z - r0h.z, r0h.z);
                a.z = fmaf(wx_p, th - tl, tl);
            }
            {
                float tl = fmaf(wy_p, r1l.w - r0l.w, r0l.w);
                float th = fmaf(wy_p, r1h.w - r0h.w, r0h.w);
                a.w = fmaf(wx_p, th - tl, tl);
            }
            *reinterpret_cast<float4*>(dst + 4 * f) = a;   // linear STS.128
        }
    };

    float m = -1e30f, se = 0.f, sx = 0.f, sy = 0.f;

    const size_t obase = (size_t)b * (Kv * Hv * Wv) + (size_t)y * Wv + x;
    const size_t ostride = (size_t)Hv * Wv;

    // ---- prologue: candidate 0 params + load into buf 0 ----
    float ox_c = __ldg(offx + obase);
    float oy_c = __ldg(offy + obase);
    publish(ox_c, oy_c, 0);
    float ox_n = __ldg(offx + obase + ostride);
    float oy_n = __ldg(offy + obase + ostride);
    __syncwarp();
    load_phase(0, stage[wid][0]);

    for (int k = 0; k < Kv; k++) {
        // Prefetch k+2 offsets (overlaps everything below).
        float ox_n2 = 0.f, oy_n2 = 0.f;
        if (k + 2 < Kv) {
            ox_n2 = __ldg(offx + obase + (size_t)(k + 2) * ostride);
            oy_n2 = __ldg(offy + obase + (size_t)(k + 2) * ostride);
        }

        // Publish params for k+1, then one sync covers: params visible AND
        // stage buf k&1 (written by last iteration's load_phase) visible.
        if (k + 1 < Kv) publish(ox_n, oy_n, (k + 1) & 1);
        __syncwarp();

        // Issue load phase k+1 into the other buffer (overlaps compute k).
        if (k + 1 < Kv) load_phase((k + 1) & 1, stage[wid][(k + 1) & 1]);

        // ---- compute phase k from buf k&1 ----
        float s[9];
#pragma unroll
        for (int i = 0; i < 9; i++) s[i] = 0.f;

        const float* mybuf = stage[wid][k & 1] + 36 * lane;
#pragma unroll
        for (int i = 0; i < 9; i++) {
            float4 a = *reinterpret_cast<const float4*>(mybuf + 4 * i);
            const int gp = i / 3;        // sampled-channel group
            const int r  = i - gp * 3;   // quad index within group
#pragma unroll
            for (int g = 0; g < 3; g++) {
                const float* f = F + 12 * g + 4 * r;
                s[3 * g + gp] += fabsf(f[0] - a.x) + fabsf(f[1] - a.y)
                               + fabsf(f[2] - a.z) + fabsf(f[3] - a.w);
            }
        }

        float smin = s[0];
#pragma unroll
        for (int i = 1; i < 9; i++) smin = fminf(smin, s[i]);

        float t = smin * (-1000.f / 12.f);

        if (t > m) {
            float c = __expf(m - t);
            se *= c; sx *= c; sy *= c;
            m = t;
        }
        float e = __expf(t - m);
        se += e;
        sx = fmaf(e, ox_c, sx);
        sy = fmaf(e, oy_c, sy);

        ox_c = ox_n;  oy_c = oy_n;
        ox_n = ox_n2; oy_n = oy_n2;
    }

    float ox = sx / se;
    float oy = sy / se;
    ox = fminf(fmaxf(ox + (float)x, 0.f), (float)(Wv - 1)) - (float)x;
    oy = fminf(fmaxf(oy + (float)y, 0.f), (float)(Hv - 1)) - (float)y;

    const size_t pix = ((size_t)b * Hv + y) * Wv + x;
    out[pix] = ox;
    out[(size_t)Bv * Hv * Wv + pix] = oy;
}

extern "C" void kernel_launch(void* const* d_in, const int* in_sizes, int n_in,
                              void* d_out, int out_size) {
    const float* features = (const float*)d_in[0];
    const float* offset_x = (const float*)d_in[1];
    const float* offset_y = (const float*)d_in[2];
    float* out = (float*)d_out;

    dim3 tgrid(Wv / 128, Hv, Bv);
    transpose_kernel<<<tgrid, 256>>>(features);

    int total = Bv * Hv * Wv;
    eval_kernel<<<total / 128, 128>>>(features, offset_x, offset_y, out);
}

// round 15
// speedup vs baseline: 1.4168x; 1.4168x over previous
#include <cuda_runtime.h>
#include <cuda_bf16.h>

#define Bv 2
#define Cv 36
#define Hv 512
#define Wv 512
#define Kv 9

// Transposed features fp32: [B, H, W, C]; one pixel = 144B contiguous.
__device__ float g_featT[(size_t)Bv * Hv * Wv * Cv];

// ---------------------------------------------------------------------------
// Transpose [B,C,H,W] -> [B,H,W,C]; float4 reads AND float4 writes.
// ---------------------------------------------------------------------------
__global__ __launch_bounds__(256) void transpose_kernel(const float* __restrict__ feat) {
    __shared__ float tile[Cv][129];
    int b = blockIdx.z;
    int h = blockIdx.y;
    int w0 = blockIdx.x * 128;

    const float4* src = reinterpret_cast<const float4*>(feat);
    for (int i = threadIdx.x; i < Cv * 32; i += 256) {
        int c  = i >> 5;
        int w4 = i & 31;
        float4 v = src[((((size_t)b * Cv + c) * Hv + h) * Wv + w0) / 4 + w4];
        tile[c][4 * w4 + 0] = v.x;
        tile[c][4 * w4 + 1] = v.y;
        tile[c][4 * w4 + 2] = v.z;
        tile[c][4 * w4 + 3] = v.w;
    }
    __syncthreads();

    float4* outp = reinterpret_cast<float4*>(
        g_featT + (((size_t)b * Hv + h) * Wv + w0) * Cv);
    for (int e = threadIdx.x; e < 128 * 9; e += 256) {
        int w = e / 9;
        int q = e - w * 9;
        float4 v;
        v.x = tile[4 * q + 0][w];
        v.y = tile[4 * q + 1][w];
        v.z = tile[4 * q + 2][w];
        v.w = tile[4 * q + 3][w];
        outp[e] = v;
    }
}

// ---------------------------------------------------------------------------
// Eval kernel (round-11 structure: single-buffer stage, shuffle-carried
// load-phase params). Block = 128 threads = 4 warps; warp owns 32
// x-consecutive pixels. F read coalesced from the ORIGINAL [B,C,H,W] layout.
// Per candidate (offsets prefetched one candidate ahead):
//   load phase : flat 288 quad-slots (32 px x 9 channel-quads) over 9
//                full-width iterations; lane fetches the 4 bilinear corner
//                quads, completes the blend in registers, stores the 36
//                final floats (word index 4*f -> linear STS.128).
//   compute    : lane p reads its 9 sample quads (stride 144B) and
//                accumulates the 9 group-pair L1 sums vs register F.
// ---------------------------------------------------------------------------
__global__ __launch_bounds__(128, 4) void eval_kernel(
    const float* __restrict__ feat,   // original [B,C,H,W]
    const float* __restrict__ offx,
    const float* __restrict__ offy,
    float* __restrict__ out)
{
    __shared__ float stage[4][32 * 36];

    const int tid  = blockIdx.x * 128 + threadIdx.x;
    const int lane = threadIdx.x & 31;
    const int wid  = threadIdx.x >> 5;
    const int x = tid & (Wv - 1);
    const int y = (tid >> 9) & (Hv - 1);
    const int b = tid >> 18;

    float* buf = stage[wid];
    const char* fb = (const char*)g_featT;
    const unsigned rowstride = (unsigned)(Wv * Cv * 4);   // next y-row

    // ---- F: 36 coalesced scalar loads from the original layout ----
    float F[Cv];
    {
        const float* fp = feat + (size_t)b * (Cv * Hv * Wv) + (size_t)y * Wv + x;
#pragma unroll
        for (int c = 0; c < Cv; c++)
            F[c] = __ldg(fp + (size_t)c * (Hv * Wv));
    }

    float m = -1e30f, se = 0.f, sx = 0.f, sy = 0.f;

    const size_t obase = (size_t)b * (Kv * Hv * Wv) + (size_t)y * Wv + x;
    const size_t ostride = (size_t)Hv * Wv;

    // Prefetch candidate 0 offsets.
    float oxk = __ldg(offx + obase);
    float oyk = __ldg(offy + obase);

    for (int k = 0; k < Kv; k++) {
        float ox_n = 0.f, oy_n = 0.f;
        if (k + 1 < Kv) {
            ox_n = __ldg(offx + obase + (size_t)(k + 1) * ostride);
            oy_n = __ldg(offy + obase + (size_t)(k + 1) * ostride);
        }

        float rx = fminf(fmaxf((float)x + oxk, 0.f), (float)(Wv - 1));
        float ry = fminf(fmaxf((float)y + oyk, 0.f), (float)(Hv - 1));
        int xb = min((int)floorf(rx), Wv - 2);
        int yb = min((int)floorf(ry), Hv - 2);
        float wx = rx - (float)xb;   // [0,1]
        float wy = ry - (float)yb;
        unsigned off = (unsigned)((b * Hv + yb) * Wv + xb) * 144u;

        // ---- load phase: 9 full-width iterations over 288 quad-slots ----
#pragma unroll 3
        for (int i = 0; i < 9; i++) {
            int f = 32 * i + lane;
            int p = f / 9;             // pixel within warp
            int j = f - 9 * p;         // channel-quad (0..8)
            unsigned off_p = __shfl_sync(0xffffffffu, off, p);
            float    wy_p  = __shfl_sync(0xffffffffu, wy,  p);
            float    wx_p  = __shfl_sync(0xffffffffu, wx,  p);
            const char* base = fb + off_p + ((unsigned)j << 4);
            float4 r0l = *reinterpret_cast<const float4*>(base);                    // yb  , xb
            float4 r0h = *reinterpret_cast<const float4*>(base + 144);              // yb  , xb+1
            float4 r1l = *reinterpret_cast<const float4*>(base + rowstride);        // yb+1, xb
            float4 r1h = *reinterpret_cast<const float4*>(base + rowstride + 144);  // yb+1, xb+1
            float4 a;
            {
                float tl = fmaf(wy_p, r1l.x - r0l.x, r0l.x);
                float th = fmaf(wy_p, r1h.x - r0h.x, r0h.x);
                a.x = fmaf(wx_p, th - tl, tl);
            }
            {
                float tl = fmaf(wy_p, r1l.y - r0l.y, r0l.y);
                float th = fmaf(wy_p, r1h.y - r0h.y, r0h.y);
                a.y = fmaf(wx_p, th - tl, tl);
            }
            {
                float tl = fmaf(wy_p, r1l.z - r0l.z, r0l.z);
                float th = fmaf(wy_p, r1h.z - r0h.z, r0h.z);
                a.z = fmaf(wx_p, th - tl, tl);
            }
            {
                float tl = fmaf(wy_p, r1l.w - r0l.w, r0l.w);
                float th = fmaf(wy_p, r1h.w - r0h.w, r0h.w);
                a.w = fmaf(wx_p, th - tl, tl);
            }
            *reinterpret_cast<float4*>(buf + 4 * f) = a;   // linear STS.128
        }
        __syncwarp();

        // ---- compute phase: lane p accumulates 9 group-pair L1 sums ----
        float s[9];
#pragma unroll
        for (int i = 0; i < 9; i++) s[i] = 0.f;

        const float* mybuf = buf + 36 * lane;
#pragma unroll
        for (int i = 0; i < 9; i++) {
            float4 a = *reinterpret_cast<const float4*>(mybuf + 4 * i);
            const int gp = i / 3;        // sampled-channel group
            const int r  = i - gp * 3;   // quad index within group
#pragma unroll
            for (int g = 0; g < 3; g++) {
                const float* f = F + 12 * g + 4 * r;
                s[3 * g + gp] += fabsf(f[0] - a.x) + fabsf(f[1] - a.y)
                               + fabsf(f[2] - a.z) + fabsf(f[3] - a.w);
            }
        }

        float smin = s[0];
#pragma unroll
        for (int i = 1; i < 9; i++) smin = fminf(smin, s[i]);

        float t = smin * (-1000.f / 12.f);

        if (t > m) {
            float c = __expf(m - t);
            se *= c; sx *= c; sy *= c;
            m = t;
        }
        float e = __expf(t - m);
        se += e;
        sx = fmaf(e, oxk, sx);
        sy = fmaf(e, oyk, sy);

        oxk = ox_n;
        oyk = oy_n;

        __syncwarp();  // stage reuse barrier before next candidate
    }

    float ox = sx / se;
    float oy = sy / se;
    ox = fminf(fmaxf(ox + (float)x, 0.f), (float)(Wv - 1)) - (float)x;
    oy = fminf(fmaxf(oy + (float)y, 0.f), (float)(Hv - 1)) - (float)y;

    const size_t pix = ((size_t)b * Hv + y) * Wv + x;
    out[pix] = ox;
    out[(size_t)Bv * Hv * Wv + pix] = oy;
}

extern "C" void kernel_launch(void* const* d_in, const int* in_sizes, int n_in,
                              void* d_out, int out_size) {
    const float* features = (const float*)d_in[0];
    const float* offset_x = (const float*)d_in[1];
    const float* offset_y = (const float*)d_in[2];
    float* out = (float*)d_out;

    dim3 tgrid(Wv / 128, Hv, Bv);
    transpose_kernel<<<tgrid, 256>>>(features);

    int total = Bv * Hv * Wv;
    eval_kernel<<<total / 128, 128>>>(features, offset_x, offset_y, out);
}

// round 17
// speedup vs baseline: 1.4280x; 1.0079x over previous
#include <cuda_runtime.h>
#include <cuda_bf16.h>

#define Bv 2
#define Cv 36
#define Hv 512
#define Wv 512
#define Kv 9

// Transposed features fp32: [B, H, W, C]; one pixel = 144B contiguous.
__device__ float g_featT[(size_t)Bv * Hv * Wv * Cv];

// ---------------------------------------------------------------------------
// Transpose [B,C,H,W] -> [B,H,W,C]; float4 reads AND float4 writes.
// ---------------------------------------------------------------------------
__global__ __launch_bounds__(256) void transpose_kernel(const float* __restrict__ feat) {
    __shared__ float tile[Cv][129];
    int b = blockIdx.z;
    int h = blockIdx.y;
    int w0 = blockIdx.x * 128;

    const float4* src = reinterpret_cast<const float4*>(feat);
    for (int i = threadIdx.x; i < Cv * 32; i += 256) {
        int c  = i >> 5;
        int w4 = i & 31;
        float4 v = src[((((size_t)b * Cv + c) * Hv + h) * Wv + w0) / 4 + w4];
        tile[c][4 * w4 + 0] = v.x;
        tile[c][4 * w4 + 1] = v.y;
        tile[c][4 * w4 + 2] = v.z;
        tile[c][4 * w4 + 3] = v.w;
    }
    __syncthreads();

    float4* outp = reinterpret_cast<float4*>(
        g_featT + (((size_t)b * Hv + h) * Wv + w0) * Cv);
    for (int e = threadIdx.x; e < 128 * 9; e += 256) {
        int w = e / 9;
        int q = e - w * 9;
        float4 v;
        v.x = tile[4 * q + 0][w];
        v.y = tile[4 * q + 1][w];
        v.z = tile[4 * q + 2][w];
        v.w = tile[4 * q + 3][w];
        outp[e] = v;
    }
}

// ---------------------------------------------------------------------------
// Eval kernel: single-buffer stage with LDS-first pipelining.
// Per candidate k:
//   1. read the 9 staged quads of k into registers (LDS ahead of any LDG)
//   2. syncwarp -> stage buffer free
//   3. issue load phase k+1 (36 LDG + 9 STS fill the L1 queue)
//   4. distance + softmax arithmetic on held registers (in LDG shadow)
//   5. syncwarp -> STS of k+1 visible for next iteration's LDS
// ---------------------------------------------------------------------------
__global__ __launch_bounds__(128, 4) void eval_kernel(
    const float* __restrict__ feat,   // original [B,C,H,W]
    const float* __restrict__ offx,
    const float* __restrict__ offy,
    float* __restrict__ out)
{
    __shared__ float stage[4][32 * 36];

    const int tid  = blockIdx.x * 128 + threadIdx.x;
    const int lane = threadIdx.x & 31;
    const int wid  = threadIdx.x >> 5;
    const int x = tid & (Wv - 1);
    const int y = (tid >> 9) & (Hv - 1);
    const int b = tid >> 18;

    float* buf = stage[wid];
    const char* fb = (const char*)g_featT;
    const unsigned rowstride = (unsigned)(Wv * Cv * 4);   // next y-row

    // ---- F: 36 coalesced scalar loads from the original layout ----
    float F[Cv];
    {
        const float* fp = feat + (size_t)b * (Cv * Hv * Wv) + (size_t)y * Wv + x;
#pragma unroll
        for (int c = 0; c < Cv; c++)
            F[c] = __ldg(fp + (size_t)c * (Hv * Wv));
    }

    // One candidate's load phase: 9 full-width iterations over 288 quad-slots.
    auto load_phase = [&](float oxk, float oyk) {
        float rx = fminf(fmaxf((float)x + oxk, 0.f), (float)(Wv - 1));
        float ry = fminf(fmaxf((float)y + oyk, 0.f), (float)(Hv - 1));
        int xb = min((int)floorf(rx), Wv - 2);
        int yb = min((int)floorf(ry), Hv - 2);
        float wx = rx - (float)xb;   // [0,1]
        float wy = ry - (float)yb;
        unsigned off = (unsigned)((b * Hv + yb) * Wv + xb) * 144u;
#pragma unroll 3
        for (int i = 0; i < 9; i++) {
            int f = 32 * i + lane;
            int p = f / 9;             // pixel within warp
            int j = f - 9 * p;         // channel-quad (0..8)
            unsigned off_p = __shfl_sync(0xffffffffu, off, p);
            float    wy_p  = __shfl_sync(0xffffffffu, wy,  p);
            float    wx_p  = __shfl_sync(0xffffffffu, wx,  p);
            const char* base = fb + off_p + ((unsigned)j << 4);
            float4 r0l = *reinterpret_cast<const float4*>(base);                    // yb  , xb
            float4 r0h = *reinterpret_cast<const float4*>(base + 144);              // yb  , xb+1
            float4 r1l = *reinterpret_cast<const float4*>(base + rowstride);        // yb+1, xb
            float4 r1h = *reinterpret_cast<const float4*>(base + rowstride + 144);  // yb+1, xb+1
            float4 a;
            {
                float tl = fmaf(wy_p, r1l.x - r0l.x, r0l.x);
                float th = fmaf(wy_p, r1h.x - r0h.x, r0h.x);
                a.x = fmaf(wx_p, th - tl, tl);
            }
            {
                float tl = fmaf(wy_p, r1l.y - r0l.y, r0l.y);
                float th = fmaf(wy_p, r1h.y - r0h.y, r0h.y);
                a.y = fmaf(wx_p, th - tl, tl);
            }
            {
                float tl = fmaf(wy_p, r1l.z - r0l.z, r0l.z);
                float th = fmaf(wy_p, r1h.z - r0h.z, r0h.z);
                a.z = fmaf(wx_p, th - tl, tl);
            }
            {
                float tl = fmaf(wy_p, r1l.w - r0l.w, r0l.w);
                float th = fmaf(wy_p, r1h.w - r0h.w, r0h.w);
                a.w = fmaf(wx_p, th - tl, tl);
            }
            *reinterpret_cast<float4*>(buf + 4 * f) = a;   // linear STS.128
        }
    };

    float m = -1e30f, se = 0.f, sx = 0.f, sy = 0.f;

    const size_t obase = (size_t)b * (Kv * Hv * Wv) + (size_t)y * Wv + x;
    const size_t ostride = (size_t)Hv * Wv;

    // ---- prologue: load candidate 0 into the stage ----
    float ox_c = __ldg(offx + obase);
    float oy_c = __ldg(offy + obase);
    load_phase(ox_c, oy_c);
    float ox_n = __ldg(offx + obase + ostride);
    float oy_n = __ldg(offy + obase + ostride);
    __syncwarp();

    const float* mybuf = buf + 36 * lane;

    for (int k = 0; k < Kv; k++) {
        // 1. Pull candidate k's 9 sample quads into registers (LDS first).
        float4 a[9];
#pragma unroll
        for (int i = 0; i < 9; i++)
            a[i] = *reinterpret_cast<const float4*>(mybuf + 4 * i);

        // Prefetch k+2 offsets.
        float ox_n2 = 0.f, oy_n2 = 0.f;
        if (k + 2 < Kv) {
            ox_n2 = __ldg(offx + obase + (size_t)(k + 2) * ostride);
            oy_n2 = __ldg(offy + obase + (size_t)(k + 2) * ostride);
        }

        // 2. Buffer is free once every lane has read.
        __syncwarp();

        // 3. Issue load phase k+1 (fills L1 queue; overlaps step 4).
        if (k + 1 < Kv) load_phase(ox_n, oy_n);

        // 4. Arithmetic on held registers.
        float s[9];
#pragma unroll
        for (int i = 0; i < 9; i++) s[i] = 0.f;

#pragma unroll
        for (int i = 0; i < 9; i++) {
            const int gp = i / 3;        // sampled-channel group
            const int r  = i - gp * 3;   // quad index within group
#pragma unroll
            for (int g = 0; g < 3; g++) {
                const float* f = F + 12 * g + 4 * r;
                s[3 * g + gp] += fabsf(f[0] - a[i].x) + fabsf(f[1] - a[i].y)
                               + fabsf(f[2] - a[i].z) + fabsf(f[3] - a[i].w);
            }
        }

        float smin = s[0];
#pragma unroll
        for (int i = 1; i < 9; i++) smin = fminf(smin, s[i]);

        float t = smin * (-1000.f / 12.f);

        if (t > m) {
            float c = __expf(m - t);
            se *= c; sx *= c; sy *= c;
            m = t;
        }
        float e = __expf(t - m);
        se += e;
        sx = fmaf(e, ox_c, sx);
        sy = fmaf(e, oy_c, sy);

        ox_c = ox_n;  oy_c = oy_n;
        ox_n = ox_n2; oy_n = oy_n2;

        // 5. STS of k+1 visible before next iteration's LDS.
        __syncwarp();
    }

    float ox = sx / se;
    float oy = sy / se;
    ox = fminf(fmaxf(ox + (float)x, 0.f), (float)(Wv - 1)) - (float)x;
    oy = fminf(fmaxf(oy + (float)y, 0.f), (float)(Hv - 1)) - (float)y;

    const size_t pix = ((size_t)b * Hv + y) * Wv + x;
    out[pix] = ox;
    out[(size_t)Bv * Hv * Wv + pix] = oy;
}

extern "C" void kernel_launch(void* const* d_in, const int* in_sizes, int n_in,
                              void* d_out, int out_size) {
    const float* features = (const float*)d_in[0];
    const float* offset_x = (const float*)d_in[1];
    const float* offset_y = (const float*)d_in[2];
    float* out = (float*)d_out;

    dim3 tgrid(Wv / 128, Hv, Bv);
    transpose_kernel<<<tgrid, 256>>>(features);

    int total = Bv * Hv * Wv;
    eval_kernel<<<total / 128, 128>>>(features, offset_x, offset_y, out);
}